// round 1
// baseline (speedup 1.0000x reference)
#include <cuda_runtime.h>
#include <math.h>

// Problem dims (fixed by setup_inputs): nx=ny=8192, d=1024, K=512, n_iters=50
#define NX 8192
#define D_DIM 1024
#define KANC 512
#define NITERS 50
#define COLCH 64           // row-chunks for the column-lse pass
#define EPS_INV 20.0f      // 1/0.05

// ---------------- scratch (static device memory; no allocations) -------------
__device__ __align__(16) float g_M[(size_t)NX * NX];       // cos/eps, 256 MB
__device__ __align__(16) float g_SimX[(size_t)NX * KANC];  // 16 MB
__device__ __align__(16) float g_SimY[(size_t)NX * KANC];  // 16 MB
__device__ __align__(16) float g_invX[NX];
__device__ __align__(16) float g_invY[NX];
__device__ __align__(16) float g_invAX[KANC];
__device__ __align__(16) float g_invAY[KANC];
__device__ __align__(16) float g_invSX[NX];
__device__ __align__(16) float g_invSY[NX];
__device__ __align__(16) float g_u[NX];   // u' = u/eps
__device__ __align__(16) float g_v[NX];   // v' = v/eps
__device__ __align__(16) float g_pm[(size_t)COLCH * NX];   // column-pass partial max
__device__ __align__(16) float g_ps[(size_t)COLCH * NX];   // column-pass partial sum

// ---------------- row L2-norm (inverse norms) --------------------------------
__global__ void __launch_bounds__(256) rownorm_kernel(const float* __restrict__ A,
                                                      float* __restrict__ inv, int ncols) {
    int row = blockIdx.x;
    const float4* a4 = (const float4*)(A + (size_t)row * ncols);
    int n4 = ncols >> 2;
    float s = 0.f;
    for (int c = threadIdx.x; c < n4; c += 256) {
        float4 x = a4[c];
        s += x.x * x.x + x.y * x.y + x.z * x.z + x.w * x.w;
    }
#pragma unroll
    for (int o = 16; o; o >>= 1) s += __shfl_xor_sync(0xffffffffu, s, o);
    __shared__ float red[8];
    int lane = threadIdx.x & 31, wid = threadIdx.x >> 5;
    if (lane == 0) red[wid] = s;
    __syncthreads();
    if (threadIdx.x == 0) {
        float t = 0.f;
#pragma unroll
        for (int w = 0; w < 8; w++) t += red[w];
        inv[row] = 1.0f / fmaxf(sqrtf(t), 1e-8f);
    }
}

// ---------------- NT GEMM with row/col inverse-norm scaling ------------------
// C[i,j] = alpha * sa[i] * sb[j] * sum_k A[i,k]*B[j,k]
// A: MxK row-major, B: NxK row-major. M,N multiples of 128; K multiple of 16.
#define GBM 128
#define GBN 128
#define GBK 16

__global__ void __launch_bounds__(256) gemm_nt_kernel(const float* __restrict__ A,
                                                      const float* __restrict__ B,
                                                      float* __restrict__ C,
                                                      const float* __restrict__ sa,
                                                      const float* __restrict__ sb,
                                                      int M, int N, int K, float alpha) {
    __shared__ float As[GBK][GBM + 4];
    __shared__ float Bs[GBK][GBN + 4];
    int tid = threadIdx.x;
    int bm = blockIdx.y, bn = blockIdx.x;
    const float* Ab = A + (size_t)bm * GBM * K;
    const float* Bb = B + (size_t)bn * GBN * K;

    int tx = tid & 15;   // 0..15 -> N dir
    int ty = tid >> 4;   // 0..15 -> M dir
    int lr = tid >> 2;          // 0..63 loader row
    int lc = (tid & 3) * 4;     // 0,4,8,12 loader col

    float acc[8][8];
#pragma unroll
    for (int i = 0; i < 8; i++)
#pragma unroll
        for (int j = 0; j < 8; j++) acc[i][j] = 0.f;

    for (int k0 = 0; k0 < K; k0 += GBK) {
#pragma unroll
        for (int sgm = 0; sgm < 2; sgm++) {
            int r = lr + 64 * sgm;
            float4 a4 = *(const float4*)(Ab + (size_t)r * K + k0 + lc);
            As[lc + 0][r] = a4.x; As[lc + 1][r] = a4.y;
            As[lc + 2][r] = a4.z; As[lc + 3][r] = a4.w;
            float4 b4 = *(const float4*)(Bb + (size_t)r * K + k0 + lc);
            Bs[lc + 0][r] = b4.x; Bs[lc + 1][r] = b4.y;
            Bs[lc + 2][r] = b4.z; Bs[lc + 3][r] = b4.w;
        }
        __syncthreads();
#pragma unroll
        for (int kk = 0; kk < GBK; kk++) {
            float4 a0 = *(const float4*)&As[kk][ty * 4];
            float4 a1 = *(const float4*)&As[kk][ty * 4 + 64];
            float4 b0 = *(const float4*)&Bs[kk][tx * 4];
            float4 b1 = *(const float4*)&Bs[kk][tx * 4 + 64];
            float af[8] = {a0.x, a0.y, a0.z, a0.w, a1.x, a1.y, a1.z, a1.w};
            float bf[8] = {b0.x, b0.y, b0.z, b0.w, b1.x, b1.y, b1.z, b1.w};
#pragma unroll
            for (int i = 0; i < 8; i++)
#pragma unroll
                for (int j = 0; j < 8; j++) acc[i][j] += af[i] * bf[j];
        }
        __syncthreads();
    }

    // epilogue with scaling; rows/cols come in 4+4 split tiles
#pragma unroll
    for (int ih = 0; ih < 2; ih++)
#pragma unroll
        for (int il = 0; il < 4; il++) {
            int i = ih * 4 + il;
            int row = bm * GBM + ty * 4 + ih * 64 + il;
            float si = sa[row] * alpha;
#pragma unroll
            for (int jh = 0; jh < 2; jh++) {
                int col = bn * GBN + tx * 4 + jh * 64;
                float4 o;
                o.x = acc[i][jh * 4 + 0] * si * sb[col + 0];
                o.y = acc[i][jh * 4 + 1] * si * sb[col + 1];
                o.z = acc[i][jh * 4 + 2] * si * sb[col + 2];
                o.w = acc[i][jh * 4 + 3] * si * sb[col + 3];
                *(float4*)(C + (size_t)row * N + col) = o;
            }
        }
}

// ---------------- online logsumexp helpers -----------------------------------
__device__ __forceinline__ void lse_upd(float& m, float& s, float x) {
    float mn = fmaxf(m, x);
    s = s * __expf(m - mn) + __expf(x - mn);
    m = mn;
}
__device__ __forceinline__ void lse_merge(float& m, float& s, float m2, float s2) {
    float mn = fmaxf(m, m2);
    s = s * __expf(m - mn) + s2 * __expf(m2 - mn);
    m = mn;
}

// ---------------- row pass: u'_i = log_mu - lse_j(M_ij + v'_j) ---------------
__global__ void __launch_bounds__(256) row_lse_kernel(const float* __restrict__ Mm,
                                                      const float* __restrict__ vp,
                                                      float* __restrict__ up, float log_mu) {
    int row = blockIdx.x;
    const float4* r4 = (const float4*)(Mm + (size_t)row * NX);
    const float4* v4 = (const float4*)vp;
    float m = -INFINITY, s = 0.f;
#pragma unroll
    for (int c = threadIdx.x, it = 0; it < NX / 4 / 256; it++, c += 256) {
        float4 x = r4[c];
        float4 v = v4[c];
        lse_upd(m, s, x.x + v.x);
        lse_upd(m, s, x.y + v.y);
        lse_upd(m, s, x.z + v.z);
        lse_upd(m, s, x.w + v.w);
    }
#pragma unroll
    for (int o = 16; o; o >>= 1) {
        float m2 = __shfl_xor_sync(0xffffffffu, m, o);
        float s2 = __shfl_xor_sync(0xffffffffu, s, o);
        lse_merge(m, s, m2, s2);
    }
    __shared__ float sm[8], ss[8];
    int lane = threadIdx.x & 31, wid = threadIdx.x >> 5;
    if (lane == 0) { sm[wid] = m; ss[wid] = s; }
    __syncthreads();
    if (threadIdx.x == 0) {
        float M_ = sm[0], S_ = ss[0];
#pragma unroll
        for (int w = 1; w < 8; w++) lse_merge(M_, S_, sm[w], ss[w]);
        up[row] = log_mu - (M_ + logf(S_));
    }
}

// ---------------- column pass (2-stage): v'_j = log_nu - lse_i(M_ij + u'_i) --
__global__ void __launch_bounds__(256) col_lse_partial_kernel(const float* __restrict__ Mm,
                                                              const float* __restrict__ up,
                                                              float* __restrict__ pm,
                                                              float* __restrict__ ps) {
    int j4 = blockIdx.x * 256 + threadIdx.x;         // float4 column index
    int r0 = blockIdx.y * (NX / COLCH);
    const float4* base = (const float4*)Mm + (size_t)r0 * (NX / 4) + j4;
    float m0 = -INFINITY, m1 = -INFINITY, m2 = -INFINITY, m3 = -INFINITY;
    float s0 = 0.f, s1 = 0.f, s2 = 0.f, s3 = 0.f;
#pragma unroll 4
    for (int r = 0; r < NX / COLCH; r++) {
        float4 x = base[(size_t)r * (NX / 4)];
        float u = __ldg(&up[r0 + r]);
        lse_upd(m0, s0, x.x + u);
        lse_upd(m1, s1, x.y + u);
        lse_upd(m2, s2, x.z + u);
        lse_upd(m3, s3, x.w + u);
    }
    size_t o = (size_t)blockIdx.y * NX + (size_t)j4 * 4;
    *(float4*)(pm + o) = make_float4(m0, m1, m2, m3);
    *(float4*)(ps + o) = make_float4(s0, s1, s2, s3);
}

__global__ void __launch_bounds__(256) col_combine_kernel(const float* __restrict__ pm,
                                                          const float* __restrict__ ps,
                                                          float* __restrict__ vp, float log_nu) {
    int j = blockIdx.x * 256 + threadIdx.x;
    float m = -INFINITY, s = 0.f;
#pragma unroll 8
    for (int c = 0; c < COLCH; c++) {
        float m2 = pm[(size_t)c * NX + j];
        float s2 = ps[(size_t)c * NX + j];
        lse_merge(m, s, m2, s2);
    }
    vp[j] = log_nu - (m + logf(s));
}

// ---------------- misc -------------------------------------------------------
__global__ void __launch_bounds__(256) zero_kernel(float* __restrict__ p) {
    p[blockIdx.x * 256 + threadIdx.x] = 0.f;
}

__global__ void __launch_bounds__(256) epilogue_kernel(const float* __restrict__ Mm,
                                                       const float* __restrict__ up,
                                                       const float* __restrict__ vp,
                                                       float* __restrict__ plan,
                                                       float* __restrict__ logplan) {
    int row = blockIdx.y;
    int c4 = blockIdx.x * 256 + threadIdx.x;  // 8 * 256 * 4 = 8192 cols
    size_t idx4 = (size_t)row * (NX / 4) + c4;
    float4 x = ((const float4*)Mm)[idx4];
    float4 v = ((const float4*)vp)[c4];
    float u = up[row];
    float4 lp = make_float4(x.x + v.x + u, x.y + v.y + u, x.z + v.z + u, x.w + v.w + u);
    float4 p = make_float4(__expf(lp.x), __expf(lp.y), __expf(lp.z), __expf(lp.w));
    ((float4*)plan)[idx4] = p;
    ((float4*)logplan)[idx4] = lp;
}

// ---------------- launch -----------------------------------------------------
extern "C" void kernel_launch(void* const* d_in, const int* in_sizes, int n_in,
                              void* d_out, int out_size) {
    const float* X  = (const float*)d_in[0];
    const float* Y  = (const float*)d_in[1];
    const float* aX = (const float*)d_in[2];
    const float* aY = (const float*)d_in[3];
    float* out = (float*)d_out;

    float *pM, *pSX, *pSY, *pinvX, *pinvY, *pinvAX, *pinvAY, *pinvSX, *pinvSY;
    float *pu, *pv, *ppm, *pps;
    cudaGetSymbolAddress((void**)&pM, g_M);
    cudaGetSymbolAddress((void**)&pSX, g_SimX);
    cudaGetSymbolAddress((void**)&pSY, g_SimY);
    cudaGetSymbolAddress((void**)&pinvX, g_invX);
    cudaGetSymbolAddress((void**)&pinvY, g_invY);
    cudaGetSymbolAddress((void**)&pinvAX, g_invAX);
    cudaGetSymbolAddress((void**)&pinvAY, g_invAY);
    cudaGetSymbolAddress((void**)&pinvSX, g_invSX);
    cudaGetSymbolAddress((void**)&pinvSY, g_invSY);
    cudaGetSymbolAddress((void**)&pu, g_u);
    cudaGetSymbolAddress((void**)&pv, g_v);
    cudaGetSymbolAddress((void**)&ppm, g_pm);
    cudaGetSymbolAddress((void**)&pps, g_ps);

    const float LOGMU = -9.01091270f;  // -log(8192)

    // 1) inverse row norms of inputs and anchors
    rownorm_kernel<<<NX, 256>>>(X, pinvX, D_DIM);
    rownorm_kernel<<<NX, 256>>>(Y, pinvY, D_DIM);
    rownorm_kernel<<<KANC, 256>>>(aX, pinvAX, D_DIM);
    rownorm_kernel<<<KANC, 256>>>(aY, pinvAY, D_DIM);

    // 2) similarity profiles: Sim_X = norm(X) @ norm(aX)^T  (8192 x 512)
    gemm_nt_kernel<<<dim3(KANC / GBN, NX / GBM), 256>>>(X, aX, pSX, pinvX, pinvAX,
                                                        NX, KANC, D_DIM, 1.0f);
    gemm_nt_kernel<<<dim3(KANC / GBN, NX / GBM), 256>>>(Y, aY, pSY, pinvY, pinvAY,
                                                        NX, KANC, D_DIM, 1.0f);

    // 3) inverse row norms of profiles
    rownorm_kernel<<<NX, 256>>>(pSX, pinvSX, KANC);
    rownorm_kernel<<<NX, 256>>>(pSY, pinvSY, KANC);

    // 4) M = cos(Sim_X, Sim_Y) / eps   (negC/eps in sinkhorn's notation)
    gemm_nt_kernel<<<dim3(NX / GBN, NX / GBM), 256>>>(pSX, pSY, pM, pinvSX, pinvSY,
                                                      NX, NX, KANC, EPS_INV);

    // 5) sinkhorn (log domain, scaled potentials u'=u/eps, v'=v/eps)
    zero_kernel<<<NX / 256, 256>>>(pv);
    for (int it = 0; it < NITERS; it++) {
        row_lse_kernel<<<NX, 256>>>(pM, pv, pu, LOGMU);
        col_lse_partial_kernel<<<dim3(NX / (256 * 4), COLCH), 256>>>(pM, pu, ppm, pps);
        col_combine_kernel<<<NX / 256, 256>>>(ppm, pps, pv, LOGMU);
    }

    // 6) outputs: plan then log_plan
    epilogue_kernel<<<dim3(NX / (256 * 4), NX), 256>>>(pM, pu, pv, out, out + (size_t)NX * NX);
}

// round 2
// speedup vs baseline: 1.1367x; 1.1367x over previous
#include <cuda_runtime.h>
#include <math.h>

// Problem dims (fixed by setup_inputs): nx=ny=8192, d=1024, K=512, n_iters=50
#define NX 8192
#define D_DIM 1024
#define KANC 512
#define NITERS 50
#define COLCH 64           // row-chunks for the column pass
#define EPS_INV 20.0f      // 1/0.05

// ---------------- scratch (static device memory; no allocations) -------------
__device__ __align__(16) float g_K[(size_t)NX * NX];       // exp(cos/eps), 256 MB
__device__ __align__(16) float g_SimX[(size_t)NX * KANC];  // 16 MB
__device__ __align__(16) float g_SimY[(size_t)NX * KANC];  // 16 MB
__device__ __align__(16) float g_invX[NX];
__device__ __align__(16) float g_invY[NX];
__device__ __align__(16) float g_invAX[KANC];
__device__ __align__(16) float g_invAY[KANC];
__device__ __align__(16) float g_invSX[NX];
__device__ __align__(16) float g_invSY[NX];
__device__ __align__(16) float g_a[NX];    // a = exp(u/eps)
__device__ __align__(16) float g_b[NX];    // b = exp(v/eps)
__device__ __align__(16) float g_la[NX];   // log a
__device__ __align__(16) float g_lb[NX];   // log b
__device__ __align__(16) float g_part[(size_t)COLCH * NX]; // column-pass partials

// ---------------- f32x2 helpers ----------------------------------------------
__device__ __forceinline__ unsigned long long pack2(float x, float y) {
    unsigned long long r;
    asm("mov.b64 %0, {%1, %2};" : "=l"(r) : "f"(x), "f"(y));
    return r;
}
__device__ __forceinline__ void unpack2(unsigned long long p, float& x, float& y) {
    asm("mov.b64 {%0, %1}, %2;" : "=f"(x), "=f"(y) : "l"(p));
}
__device__ __forceinline__ unsigned long long fma2(unsigned long long a,
                                                   unsigned long long b,
                                                   unsigned long long c) {
    unsigned long long d;
    asm("fma.rn.f32x2 %0, %1, %2, %3;" : "=l"(d) : "l"(a), "l"(b), "l"(c));
    return d;
}

// ---------------- row L2-norm (inverse norms) --------------------------------
__global__ void __launch_bounds__(256) rownorm_kernel(const float* __restrict__ A,
                                                      float* __restrict__ inv, int ncols) {
    int row = blockIdx.x;
    const float4* a4 = (const float4*)(A + (size_t)row * ncols);
    int n4 = ncols >> 2;
    float s = 0.f;
    for (int c = threadIdx.x; c < n4; c += 256) {
        float4 x = a4[c];
        s += x.x * x.x + x.y * x.y + x.z * x.z + x.w * x.w;
    }
#pragma unroll
    for (int o = 16; o; o >>= 1) s += __shfl_xor_sync(0xffffffffu, s, o);
    __shared__ float red[8];
    int lane = threadIdx.x & 31, wid = threadIdx.x >> 5;
    if (lane == 0) red[wid] = s;
    __syncthreads();
    if (threadIdx.x == 0) {
        float t = 0.f;
#pragma unroll
        for (int w = 0; w < 8; w++) t += red[w];
        inv[row] = 1.0f / fmaxf(sqrtf(t), 1e-8f);
    }
}

// ---------------- NT GEMM (f32x2) with scaling, optional exp -----------------
// C[i,j] = f( alpha * sa[i] * sb[j] * sum_k A[i,k]*B[j,k] ),  f = exp if do_exp
#define GBM 128
#define GBN 128
#define GBK 16

__global__ void __launch_bounds__(256) gemm_nt_kernel(const float* __restrict__ A,
                                                      const float* __restrict__ B,
                                                      float* __restrict__ C,
                                                      const float* __restrict__ sa,
                                                      const float* __restrict__ sb,
                                                      int M, int N, int K, float alpha,
                                                      int do_exp) {
    __shared__ float As[GBK][GBM + 4];
    __shared__ float Bs[GBK][GBN + 4];
    int tid = threadIdx.x;
    int bm = blockIdx.y, bn = blockIdx.x;
    const float* Ab = A + (size_t)bm * GBM * K;
    const float* Bb = B + (size_t)bn * GBN * K;

    int tx = tid & 15;   // N dir
    int ty = tid >> 4;   // M dir
    int lr = tid >> 2;          // loader row
    int lc = (tid & 3) * 4;     // loader col

    unsigned long long acc[4][8];   // [i-pair][j]
#pragma unroll
    for (int ip = 0; ip < 4; ip++)
#pragma unroll
        for (int j = 0; j < 8; j++) acc[ip][j] = 0ULL;

    for (int k0 = 0; k0 < K; k0 += GBK) {
#pragma unroll
        for (int sgm = 0; sgm < 2; sgm++) {
            int r = lr + 64 * sgm;
            float4 a4 = *(const float4*)(Ab + (size_t)r * K + k0 + lc);
            As[lc + 0][r] = a4.x; As[lc + 1][r] = a4.y;
            As[lc + 2][r] = a4.z; As[lc + 3][r] = a4.w;
            float4 b4 = *(const float4*)(Bb + (size_t)r * K + k0 + lc);
            Bs[lc + 0][r] = b4.x; Bs[lc + 1][r] = b4.y;
            Bs[lc + 2][r] = b4.z; Bs[lc + 3][r] = b4.w;
        }
        __syncthreads();
#pragma unroll
        for (int kk = 0; kk < GBK; kk++) {
            float4 a0 = *(const float4*)&As[kk][ty * 4];
            float4 a1 = *(const float4*)&As[kk][ty * 4 + 64];
            float4 b0 = *(const float4*)&Bs[kk][tx * 4];
            float4 b1 = *(const float4*)&Bs[kk][tx * 4 + 64];
            unsigned long long ap[4];
            ap[0] = pack2(a0.x, a0.y); ap[1] = pack2(a0.z, a0.w);
            ap[2] = pack2(a1.x, a1.y); ap[3] = pack2(a1.z, a1.w);
            float bf[8] = {b0.x, b0.y, b0.z, b0.w, b1.x, b1.y, b1.z, b1.w};
            unsigned long long bs2[8];
#pragma unroll
            for (int j = 0; j < 8; j++) bs2[j] = pack2(bf[j], bf[j]);
#pragma unroll
            for (int ip = 0; ip < 4; ip++)
#pragma unroll
                for (int j = 0; j < 8; j++) acc[ip][j] = fma2(ap[ip], bs2[j], acc[ip][j]);
        }
        __syncthreads();
    }

#pragma unroll
    for (int ip = 0; ip < 4; ip++)
#pragma unroll
        for (int h = 0; h < 2; h++) {
            int row = bm * GBM + ty * 4 + ((ip & 1) << 1) + h + ((ip >> 1) << 6);
            float si = sa[row] * alpha;
#pragma unroll
            for (int g = 0; g < 2; g++) {
                int col = bn * GBN + tx * 4 + (g << 6);
                float v[4];
#pragma unroll
                for (int j = 0; j < 4; j++) {
                    float lo, hi;
                    unpack2(acc[ip][g * 4 + j], lo, hi);
                    v[j] = h ? hi : lo;
                }
                float4 o;
                o.x = v[0] * si * sb[col + 0];
                o.y = v[1] * si * sb[col + 1];
                o.z = v[2] * si * sb[col + 2];
                o.w = v[3] * si * sb[col + 3];
                if (do_exp) {
                    o.x = __expf(o.x); o.y = __expf(o.y);
                    o.z = __expf(o.z); o.w = __expf(o.w);
                }
                *(float4*)(C + (size_t)row * N + col) = o;
            }
        }
}

// ---------------- row matvec: a_i = mu / sum_j K_ij b_j  (4 rows/block) ------
__global__ void __launch_bounds__(256) row_matvec_kernel(const float* __restrict__ Km,
                                                         const float* __restrict__ b,
                                                         float* __restrict__ a, float mu) {
    int r0 = blockIdx.x * 4;
    const float4* row0 = (const float4*)(Km + (size_t)r0 * NX);
    const float4* b4 = (const float4*)b;
    float s0 = 0.f, s1 = 0.f, s2 = 0.f, s3 = 0.f;
#pragma unroll 4
    for (int c = threadIdx.x, it = 0; it < NX / 4 / 256; it++, c += 256) {
        float4 bb = b4[c];
        float4 x0 = row0[c];
        float4 x1 = row0[c + (NX / 4)];
        float4 x2 = row0[c + 2 * (NX / 4)];
        float4 x3 = row0[c + 3 * (NX / 4)];
        s0 += x0.x * bb.x + x0.y * bb.y + x0.z * bb.z + x0.w * bb.w;
        s1 += x1.x * bb.x + x1.y * bb.y + x1.z * bb.z + x1.w * bb.w;
        s2 += x2.x * bb.x + x2.y * bb.y + x2.z * bb.z + x2.w * bb.w;
        s3 += x3.x * bb.x + x3.y * bb.y + x3.z * bb.z + x3.w * bb.w;
    }
#pragma unroll
    for (int o = 16; o; o >>= 1) {
        s0 += __shfl_xor_sync(0xffffffffu, s0, o);
        s1 += __shfl_xor_sync(0xffffffffu, s1, o);
        s2 += __shfl_xor_sync(0xffffffffu, s2, o);
        s3 += __shfl_xor_sync(0xffffffffu, s3, o);
    }
    __shared__ float red[8][4];
    int lane = threadIdx.x & 31, wid = threadIdx.x >> 5;
    if (lane == 0) { red[wid][0] = s0; red[wid][1] = s1; red[wid][2] = s2; red[wid][3] = s3; }
    __syncthreads();
    if (threadIdx.x < 4) {
        float t = 0.f;
#pragma unroll
        for (int w = 0; w < 8; w++) t += red[w][threadIdx.x];
        a[r0 + threadIdx.x] = mu / t;
    }
}

// ---------------- col matvec (2-stage): b_j = nu / sum_i K_ij a_i ------------
__global__ void __launch_bounds__(256) col_partial_kernel(const float* __restrict__ Km,
                                                          const float* __restrict__ a,
                                                          float* __restrict__ part) {
    int j4 = blockIdx.x * 256 + threadIdx.x;         // float4 column index
    int r0 = blockIdx.y * (NX / COLCH);
    const float4* base = (const float4*)Km + (size_t)r0 * (NX / 4) + j4;
    float4 s = make_float4(0.f, 0.f, 0.f, 0.f);
#pragma unroll 4
    for (int r = 0; r < NX / COLCH; r++) {
        float4 x = base[(size_t)r * (NX / 4)];
        float av = __ldg(&a[r0 + r]);
        s.x += x.x * av; s.y += x.y * av; s.z += x.z * av; s.w += x.w * av;
    }
    *(float4*)(part + (size_t)blockIdx.y * NX + (size_t)j4 * 4) = s;
}

__global__ void __launch_bounds__(256) col_combine_kernel(const float* __restrict__ part,
                                                          float* __restrict__ b, float nu) {
    int j = blockIdx.x * 256 + threadIdx.x;
    float t = 0.f;
#pragma unroll 8
    for (int c = 0; c < COLCH; c++) t += part[(size_t)c * NX + j];
    b[j] = nu / t;
}

// ---------------- misc -------------------------------------------------------
__global__ void __launch_bounds__(256) ones_kernel(float* __restrict__ p) {
    p[blockIdx.x * 256 + threadIdx.x] = 1.0f;
}

__global__ void __launch_bounds__(256) log_kernel(const float* __restrict__ a,
                                                  const float* __restrict__ b,
                                                  float* __restrict__ la,
                                                  float* __restrict__ lb) {
    int i = blockIdx.x * 256 + threadIdx.x;
    la[i] = __logf(a[i]);
    lb[i] = __logf(b[i]);
}

__global__ void __launch_bounds__(256) epilogue_kernel(const float* __restrict__ Km,
                                                       const float* __restrict__ a,
                                                       const float* __restrict__ b,
                                                       const float* __restrict__ la,
                                                       const float* __restrict__ lb,
                                                       float* __restrict__ plan,
                                                       float* __restrict__ logplan) {
    int row = blockIdx.y;
    int c4 = blockIdx.x * 256 + threadIdx.x;
    size_t idx4 = (size_t)row * (NX / 4) + c4;
    float4 x = ((const float4*)Km)[idx4];
    float4 bb = ((const float4*)b)[c4];
    float4 lv = ((const float4*)lb)[c4];
    float av = a[row];
    float ul = la[row];
    float4 p;
    p.x = (x.x * av) * bb.x;
    p.y = (x.y * av) * bb.y;
    p.z = (x.z * av) * bb.z;
    p.w = (x.w * av) * bb.w;
    float4 lp;
    lp.x = __logf(x.x) + ul + lv.x;
    lp.y = __logf(x.y) + ul + lv.y;
    lp.z = __logf(x.z) + ul + lv.z;
    lp.w = __logf(x.w) + ul + lv.w;
    ((float4*)plan)[idx4] = p;
    ((float4*)logplan)[idx4] = lp;
}

// ---------------- launch -----------------------------------------------------
extern "C" void kernel_launch(void* const* d_in, const int* in_sizes, int n_in,
                              void* d_out, int out_size) {
    const float* X  = (const float*)d_in[0];
    const float* Y  = (const float*)d_in[1];
    const float* aX = (const float*)d_in[2];
    const float* aY = (const float*)d_in[3];
    float* out = (float*)d_out;

    float *pK, *pSX, *pSY, *pinvX, *pinvY, *pinvAX, *pinvAY, *pinvSX, *pinvSY;
    float *pa, *pb, *pla, *plb, *ppart;
    cudaGetSymbolAddress((void**)&pK, g_K);
    cudaGetSymbolAddress((void**)&pSX, g_SimX);
    cudaGetSymbolAddress((void**)&pSY, g_SimY);
    cudaGetSymbolAddress((void**)&pinvX, g_invX);
    cudaGetSymbolAddress((void**)&pinvY, g_invY);
    cudaGetSymbolAddress((void**)&pinvAX, g_invAX);
    cudaGetSymbolAddress((void**)&pinvAY, g_invAY);
    cudaGetSymbolAddress((void**)&pinvSX, g_invSX);
    cudaGetSymbolAddress((void**)&pinvSY, g_invSY);
    cudaGetSymbolAddress((void**)&pa, g_a);
    cudaGetSymbolAddress((void**)&pb, g_b);
    cudaGetSymbolAddress((void**)&pla, g_la);
    cudaGetSymbolAddress((void**)&plb, g_lb);
    cudaGetSymbolAddress((void**)&ppart, g_part);

    const float MU = 1.0f / 8192.0f;   // = nu

    // 1) inverse row norms of inputs and anchors
    rownorm_kernel<<<NX, 256>>>(X, pinvX, D_DIM);
    rownorm_kernel<<<NX, 256>>>(Y, pinvY, D_DIM);
    rownorm_kernel<<<KANC, 256>>>(aX, pinvAX, D_DIM);
    rownorm_kernel<<<KANC, 256>>>(aY, pinvAY, D_DIM);

    // 2) similarity profiles: Sim_X = norm(X) @ norm(aX)^T  (8192 x 512)
    gemm_nt_kernel<<<dim3(KANC / GBN, NX / GBM), 256>>>(X, aX, pSX, pinvX, pinvAX,
                                                        NX, KANC, D_DIM, 1.0f, 0);
    gemm_nt_kernel<<<dim3(KANC / GBN, NX / GBM), 256>>>(Y, aY, pSY, pinvY, pinvAY,
                                                        NX, KANC, D_DIM, 1.0f, 0);

    // 3) inverse row norms of profiles
    rownorm_kernel<<<NX, 256>>>(pSX, pinvSX, KANC);
    rownorm_kernel<<<NX, 256>>>(pSY, pinvSY, KANC);

    // 4) K = exp(cos(Sim_X, Sim_Y) / eps)
    gemm_nt_kernel<<<dim3(NX / GBN, NX / GBM), 256>>>(pSX, pSY, pK, pinvSX, pinvSY,
                                                      NX, NX, KANC, EPS_INV, 1);

    // 5) sinkhorn, exp domain:  a = mu/(K b);  b = nu/(K^T a)
    ones_kernel<<<NX / 256, 256>>>(pb);
    for (int it = 0; it < NITERS; it++) {
        row_matvec_kernel<<<NX / 4, 256>>>(pK, pb, pa, MU);
        col_partial_kernel<<<dim3(NX / (256 * 4), COLCH), 256>>>(pK, pa, ppart);
        col_combine_kernel<<<NX / 256, 256>>>(ppart, pb, MU);
    }
    log_kernel<<<NX / 256, 256>>>(pa, pb, pla, plb);

    // 6) outputs: plan then log_plan
    epilogue_kernel<<<dim3(NX / (256 * 4), NX), 256>>>(pK, pa, pb, pla, plb,
                                                       out, out + (size_t)NX * NX);
}

// round 3
// speedup vs baseline: 1.4668x; 1.2904x over previous
#include <cuda_runtime.h>
#include <cuda_fp16.h>
#include <math.h>

// Problem dims (fixed by setup_inputs): nx=ny=8192, d=1024, K=512, n_iters=50
#define NX 8192
#define D_DIM 1024
#define KANC 512
#define NITERS 50
#define COLCH 64           // row-chunks for the column pass
#define EPS_INV 20.0f      // 1/0.05

// ---------------- scratch (static device memory; no allocations) -------------
__device__ __align__(16) __half g_K[(size_t)NX * NX];      // exp(cos/eps), 128 MB
__device__ __align__(16) float g_SimX[(size_t)NX * KANC];  // 16 MB
__device__ __align__(16) float g_SimY[(size_t)NX * KANC];  // 16 MB
__device__ __align__(16) float g_invX[NX];
__device__ __align__(16) float g_invY[NX];
__device__ __align__(16) float g_invAX[KANC];
__device__ __align__(16) float g_invAY[KANC];
__device__ __align__(16) float g_invSX[NX];
__device__ __align__(16) float g_invSY[NX];
__device__ __align__(16) float g_a[NX];    // a = exp(u/eps)
__device__ __align__(16) float g_b[NX];    // b = exp(v/eps)
__device__ __align__(16) float g_la[NX];   // log a
__device__ __align__(16) float g_lb[NX];   // log b
__device__ __align__(16) float g_part[(size_t)COLCH * NX]; // column-pass partials

// ---------------- f32x2 helpers ----------------------------------------------
__device__ __forceinline__ unsigned long long pack2(float x, float y) {
    unsigned long long r;
    asm("mov.b64 %0, {%1, %2};" : "=l"(r) : "f"(x), "f"(y));
    return r;
}
__device__ __forceinline__ void unpack2(unsigned long long p, float& x, float& y) {
    asm("mov.b64 {%0, %1}, %2;" : "=f"(x), "=f"(y) : "l"(p));
}
__device__ __forceinline__ unsigned long long fma2(unsigned long long a,
                                                   unsigned long long b,
                                                   unsigned long long c) {
    unsigned long long d;
    asm("fma.rn.f32x2 %0, %1, %2, %3;" : "=l"(d) : "l"(a), "l"(b), "l"(c));
    return d;
}

// ---------------- row L2-norm (inverse norms) --------------------------------
__global__ void __launch_bounds__(256) rownorm_kernel(const float* __restrict__ A,
                                                      float* __restrict__ inv, int ncols) {
    int row = blockIdx.x;
    const float4* a4 = (const float4*)(A + (size_t)row * ncols);
    int n4 = ncols >> 2;
    float s = 0.f;
    for (int c = threadIdx.x; c < n4; c += 256) {
        float4 x = a4[c];
        s += x.x * x.x + x.y * x.y + x.z * x.z + x.w * x.w;
    }
#pragma unroll
    for (int o = 16; o; o >>= 1) s += __shfl_xor_sync(0xffffffffu, s, o);
    __shared__ float red[8];
    int lane = threadIdx.x & 31, wid = threadIdx.x >> 5;
    if (lane == 0) red[wid] = s;
    __syncthreads();
    if (threadIdx.x == 0) {
        float t = 0.f;
#pragma unroll
        for (int w = 0; w < 8; w++) t += red[w];
        inv[row] = 1.0f / fmaxf(sqrtf(t), 1e-8f);
    }
}

// ---------------- NT GEMM (f32x2) with scaling; fp32 out or exp->fp16 out ----
// do_exp==0: C[i,j]  = alpha*sa[i]*sb[j]*dot   (float out)
// do_exp==1: Ch[i,j] = exp(alpha*sa[i]*sb[j]*dot)  (half out)
#define GBM 128
#define GBN 128
#define GBK 16

__global__ void __launch_bounds__(256) gemm_nt_kernel(const float* __restrict__ A,
                                                      const float* __restrict__ B,
                                                      float* __restrict__ C,
                                                      __half* __restrict__ Ch,
                                                      const float* __restrict__ sa,
                                                      const float* __restrict__ sb,
                                                      int M, int N, int K, float alpha,
                                                      int do_exp) {
    __shared__ float As[GBK][GBM + 4];
    __shared__ float Bs[GBK][GBN + 4];
    int tid = threadIdx.x;
    int bm = blockIdx.y, bn = blockIdx.x;
    const float* Ab = A + (size_t)bm * GBM * K;
    const float* Bb = B + (size_t)bn * GBN * K;

    int tx = tid & 15;   // N dir
    int ty = tid >> 4;   // M dir
    int lr = tid >> 2;          // loader row
    int lc = (tid & 3) * 4;     // loader col

    unsigned long long acc[4][8];   // [i-pair][j]
#pragma unroll
    for (int ip = 0; ip < 4; ip++)
#pragma unroll
        for (int j = 0; j < 8; j++) acc[ip][j] = 0ULL;

    for (int k0 = 0; k0 < K; k0 += GBK) {
#pragma unroll
        for (int sgm = 0; sgm < 2; sgm++) {
            int r = lr + 64 * sgm;
            float4 a4 = *(const float4*)(Ab + (size_t)r * K + k0 + lc);
            As[lc + 0][r] = a4.x; As[lc + 1][r] = a4.y;
            As[lc + 2][r] = a4.z; As[lc + 3][r] = a4.w;
            float4 b4 = *(const float4*)(Bb + (size_t)r * K + k0 + lc);
            Bs[lc + 0][r] = b4.x; Bs[lc + 1][r] = b4.y;
            Bs[lc + 2][r] = b4.z; Bs[lc + 3][r] = b4.w;
        }
        __syncthreads();
#pragma unroll
        for (int kk = 0; kk < GBK; kk++) {
            float4 a0 = *(const float4*)&As[kk][ty * 4];
            float4 a1 = *(const float4*)&As[kk][ty * 4 + 64];
            float4 b0 = *(const float4*)&Bs[kk][tx * 4];
            float4 b1 = *(const float4*)&Bs[kk][tx * 4 + 64];
            unsigned long long ap[4];
            ap[0] = pack2(a0.x, a0.y); ap[1] = pack2(a0.z, a0.w);
            ap[2] = pack2(a1.x, a1.y); ap[3] = pack2(a1.z, a1.w);
            float bf[8] = {b0.x, b0.y, b0.z, b0.w, b1.x, b1.y, b1.z, b1.w};
            unsigned long long bs2[8];
#pragma unroll
            for (int j = 0; j < 8; j++) bs2[j] = pack2(bf[j], bf[j]);
#pragma unroll
            for (int ip = 0; ip < 4; ip++)
#pragma unroll
                for (int j = 0; j < 8; j++) acc[ip][j] = fma2(ap[ip], bs2[j], acc[ip][j]);
        }
        __syncthreads();
    }

#pragma unroll
    for (int ip = 0; ip < 4; ip++)
#pragma unroll
        for (int h = 0; h < 2; h++) {
            int row = bm * GBM + ty * 4 + ((ip & 1) << 1) + h + ((ip >> 1) << 6);
            float si = sa[row] * alpha;
#pragma unroll
            for (int g = 0; g < 2; g++) {
                int col = bn * GBN + tx * 4 + (g << 6);
                float v[4];
#pragma unroll
                for (int j = 0; j < 4; j++) {
                    float lo, hi;
                    unpack2(acc[ip][g * 4 + j], lo, hi);
                    v[j] = h ? hi : lo;
                }
                float4 o;
                o.x = v[0] * si * sb[col + 0];
                o.y = v[1] * si * sb[col + 1];
                o.z = v[2] * si * sb[col + 2];
                o.w = v[3] * si * sb[col + 3];
                if (do_exp) {
                    __half2 h0 = __floats2half2_rn(__expf(o.x), __expf(o.y));
                    __half2 h1 = __floats2half2_rn(__expf(o.z), __expf(o.w));
                    uint2 pk;
                    pk.x = *(unsigned int*)&h0;
                    pk.y = *(unsigned int*)&h1;
                    *(uint2*)(Ch + (size_t)row * N + col) = pk;
                } else {
                    *(float4*)(C + (size_t)row * N + col) = o;
                }
            }
        }
}

// ---------------- row matvec: a_i = mu / sum_j K_ij b_j  (4 rows/block) ------
__global__ void __launch_bounds__(256) row_matvec_kernel(const __half* __restrict__ Km,
                                                         const float* __restrict__ b,
                                                         float* __restrict__ a, float mu) {
    int r0 = blockIdx.x * 4;
    const uint4* row0 = (const uint4*)(Km + (size_t)r0 * NX);   // 1024 uint4 per row
    const float4* b4 = (const float4*)b;
    float s0 = 0.f, s1 = 0.f, s2 = 0.f, s3 = 0.f;
#pragma unroll
    for (int it = 0; it < NX / 8 / 256; it++) {
        int c = it * 256 + threadIdx.x;
        float4 bb0 = b4[c * 2], bb1 = b4[c * 2 + 1];
        float bv[8] = {bb0.x, bb0.y, bb0.z, bb0.w, bb1.x, bb1.y, bb1.z, bb1.w};
#pragma unroll
        for (int r = 0; r < 4; r++) {
            uint4 x = row0[c + r * (NX / 8)];
            const __half2* hx = (const __half2*)&x;
            float acc = 0.f;
#pragma unroll
            for (int q = 0; q < 4; q++) {
                float2 f = __half22float2(hx[q]);
                acc += f.x * bv[q * 2] + f.y * bv[q * 2 + 1];
            }
            if (r == 0) s0 += acc;
            else if (r == 1) s1 += acc;
            else if (r == 2) s2 += acc;
            else s3 += acc;
        }
    }
#pragma unroll
    for (int o = 16; o; o >>= 1) {
        s0 += __shfl_xor_sync(0xffffffffu, s0, o);
        s1 += __shfl_xor_sync(0xffffffffu, s1, o);
        s2 += __shfl_xor_sync(0xffffffffu, s2, o);
        s3 += __shfl_xor_sync(0xffffffffu, s3, o);
    }
    __shared__ float red[8][4];
    int lane = threadIdx.x & 31, wid = threadIdx.x >> 5;
    if (lane == 0) { red[wid][0] = s0; red[wid][1] = s1; red[wid][2] = s2; red[wid][3] = s3; }
    __syncthreads();
    if (threadIdx.x < 4) {
        float t = 0.f;
#pragma unroll
        for (int w = 0; w < 8; w++) t += red[w][threadIdx.x];
        a[r0 + threadIdx.x] = mu / t;
    }
}

// ---------------- col matvec (2-stage): b_j = nu / sum_i K_ij a_i ------------
__global__ void __launch_bounds__(256) col_partial_kernel(const __half* __restrict__ Km,
                                                          const float* __restrict__ a,
                                                          float* __restrict__ part) {
    int j8 = blockIdx.x * 256 + threadIdx.x;          // uint4 column index (8 cols)
    int r0 = blockIdx.y * (NX / COLCH);
    const uint4* base = (const uint4*)Km + (size_t)r0 * (NX / 8) + j8;
    float s[8];
#pragma unroll
    for (int q = 0; q < 8; q++) s[q] = 0.f;
#pragma unroll 4
    for (int r = 0; r < NX / COLCH; r++) {
        uint4 x = base[(size_t)r * (NX / 8)];
        float av = __ldg(&a[r0 + r]);
        const __half2* hx = (const __half2*)&x;
#pragma unroll
        for (int q = 0; q < 4; q++) {
            float2 f = __half22float2(hx[q]);
            s[q * 2] += f.x * av;
            s[q * 2 + 1] += f.y * av;
        }
    }
    size_t o = (size_t)blockIdx.y * NX + (size_t)j8 * 8;
    *(float4*)(part + o) = make_float4(s[0], s[1], s[2], s[3]);
    *(float4*)(part + o + 4) = make_float4(s[4], s[5], s[6], s[7]);
}

__global__ void __launch_bounds__(256) col_combine_kernel(const float* __restrict__ part,
                                                          float* __restrict__ b, float nu) {
    int j = blockIdx.x * 256 + threadIdx.x;
    float t = 0.f;
#pragma unroll 8
    for (int c = 0; c < COLCH; c++) t += part[(size_t)c * NX + j];
    b[j] = nu / t;
}

// ---------------- misc -------------------------------------------------------
__global__ void __launch_bounds__(256) ones_kernel(float* __restrict__ p) {
    p[blockIdx.x * 256 + threadIdx.x] = 1.0f;
}

__global__ void __launch_bounds__(256) log_kernel(const float* __restrict__ a,
                                                  const float* __restrict__ b,
                                                  float* __restrict__ la,
                                                  float* __restrict__ lb) {
    int i = blockIdx.x * 256 + threadIdx.x;
    la[i] = __logf(a[i]);
    lb[i] = __logf(b[i]);
}

__global__ void __launch_bounds__(256) epilogue_kernel(const __half* __restrict__ Km,
                                                       const float* __restrict__ a,
                                                       const float* __restrict__ b,
                                                       const float* __restrict__ la,
                                                       const float* __restrict__ lb,
                                                       float* __restrict__ plan,
                                                       float* __restrict__ logplan) {
    int row = blockIdx.y;
    int c8 = blockIdx.x * 256 + threadIdx.x;      // uint4 index (8 cols): 4 blocks in x
    size_t kidx = (size_t)row * (NX / 8) + c8;
    uint4 x = ((const uint4*)Km)[kidx];
    const __half2* hx = (const __half2*)&x;
    float av = a[row];
    float ul = la[row];
    float kf[8];
#pragma unroll
    for (int q = 0; q < 4; q++) {
        float2 f = __half22float2(hx[q]);
        kf[q * 2] = f.x; kf[q * 2 + 1] = f.y;
    }
    float4 bb0 = ((const float4*)b)[c8 * 2];
    float4 bb1 = ((const float4*)b)[c8 * 2 + 1];
    float4 lv0 = ((const float4*)lb)[c8 * 2];
    float4 lv1 = ((const float4*)lb)[c8 * 2 + 1];
    float bv[8] = {bb0.x, bb0.y, bb0.z, bb0.w, bb1.x, bb1.y, bb1.z, bb1.w};
    float lvv[8] = {lv0.x, lv0.y, lv0.z, lv0.w, lv1.x, lv1.y, lv1.z, lv1.w};
    float p[8], lp[8];
#pragma unroll
    for (int q = 0; q < 8; q++) {
        p[q] = (kf[q] * av) * bv[q];
        lp[q] = __logf(kf[q]) + ul + lvv[q];
    }
    size_t o4 = (size_t)row * (NX / 4) + (size_t)c8 * 2;
    ((float4*)plan)[o4] = make_float4(p[0], p[1], p[2], p[3]);
    ((float4*)plan)[o4 + 1] = make_float4(p[4], p[5], p[6], p[7]);
    ((float4*)logplan)[o4] = make_float4(lp[0], lp[1], lp[2], lp[3]);
    ((float4*)logplan)[o4 + 1] = make_float4(lp[4], lp[5], lp[6], lp[7]);
}

// ---------------- launch -----------------------------------------------------
extern "C" void kernel_launch(void* const* d_in, const int* in_sizes, int n_in,
                              void* d_out, int out_size) {
    const float* X  = (const float*)d_in[0];
    const float* Y  = (const float*)d_in[1];
    const float* aX = (const float*)d_in[2];
    const float* aY = (const float*)d_in[3];
    float* out = (float*)d_out;

    __half* pK;
    float *pSX, *pSY, *pinvX, *pinvY, *pinvAX, *pinvAY, *pinvSX, *pinvSY;
    float *pa, *pb, *pla, *plb, *ppart;
    cudaGetSymbolAddress((void**)&pK, g_K);
    cudaGetSymbolAddress((void**)&pSX, g_SimX);
    cudaGetSymbolAddress((void**)&pSY, g_SimY);
    cudaGetSymbolAddress((void**)&pinvX, g_invX);
    cudaGetSymbolAddress((void**)&pinvY, g_invY);
    cudaGetSymbolAddress((void**)&pinvAX, g_invAX);
    cudaGetSymbolAddress((void**)&pinvAY, g_invAY);
    cudaGetSymbolAddress((void**)&pinvSX, g_invSX);
    cudaGetSymbolAddress((void**)&pinvSY, g_invSY);
    cudaGetSymbolAddress((void**)&pa, g_a);
    cudaGetSymbolAddress((void**)&pb, g_b);
    cudaGetSymbolAddress((void**)&pla, g_la);
    cudaGetSymbolAddress((void**)&plb, g_lb);
    cudaGetSymbolAddress((void**)&ppart, g_part);

    const float MU = 1.0f / 8192.0f;   // = nu

    // 1) inverse row norms of inputs and anchors
    rownorm_kernel<<<NX, 256>>>(X, pinvX, D_DIM);
    rownorm_kernel<<<NX, 256>>>(Y, pinvY, D_DIM);
    rownorm_kernel<<<KANC, 256>>>(aX, pinvAX, D_DIM);
    rownorm_kernel<<<KANC, 256>>>(aY, pinvAY, D_DIM);

    // 2) similarity profiles: Sim_X = norm(X) @ norm(aX)^T  (8192 x 512)
    gemm_nt_kernel<<<dim3(KANC / GBN, NX / GBM), 256>>>(X, aX, pSX, (__half*)0, pinvX, pinvAX,
                                                        NX, KANC, D_DIM, 1.0f, 0);
    gemm_nt_kernel<<<dim3(KANC / GBN, NX / GBM), 256>>>(Y, aY, pSY, (__half*)0, pinvY, pinvAY,
                                                        NX, KANC, D_DIM, 1.0f, 0);

    // 3) inverse row norms of profiles
    rownorm_kernel<<<NX, 256>>>(pSX, pinvSX, KANC);
    rownorm_kernel<<<NX, 256>>>(pSY, pinvSY, KANC);

    // 4) K = exp(cos(Sim_X, Sim_Y) / eps), stored fp16
    gemm_nt_kernel<<<dim3(NX / GBN, NX / GBM), 256>>>(pSX, pSY, (float*)0, pK, pinvSX, pinvSY,
                                                      NX, NX, KANC, EPS_INV, 1);

    // 5) sinkhorn, exp domain:  a = mu/(K b);  b = nu/(K^T a)
    ones_kernel<<<NX / 256, 256>>>(pb);
    for (int it = 0; it < NITERS; it++) {
        row_matvec_kernel<<<NX / 4, 256>>>(pK, pb, pa, MU);
        col_partial_kernel<<<dim3(NX / (256 * 8), COLCH), 256>>>(pK, pa, ppart);
        col_combine_kernel<<<NX / 256, 256>>>(ppart, pb, MU);
    }
    log_kernel<<<NX / 256, 256>>>(pa, pb, pla, plb);

    // 6) outputs: plan then log_plan
    epilogue_kernel<<<dim3(NX / (256 * 8), NX), 256>>>(pK, pa, pb, pla, plb,
                                                       out, out + (size_t)NX * NX);
}